// round 17
// baseline (speedup 1.0000x reference)
#include <cuda_runtime.h>
#include <cstdint>

// ContactMapGeneration: mean/s_obj + FPS + gather, TWO batches per cluster.
// 8 clusters x 8 CTAs; batch A in registers (R16 scan), batch B in SMEM.
// Two DSMEM-mbarrier pipelines; B's scan hides A's barrier latency and
// vice versa. B winner coords ride the exchange payload (from SMEM);
// A winner coords via uniform __ldg.

#define CLUSTERSZ 8
#define TPB 512
#define NPAIR 13                 // batch A: 26 slots; slot 25 padding
#define NSLOTB 25                // batch B: 25 slots; slot 24 guarded
#define STRIDE (CLUSTERSZ * TPB) // 4096 threads per batch
#define MAXNP 2048
#define BIGF 1e10f
#define BSLOTS (NSLOTB * TPB)    // 12800 entries per SMEM array

typedef unsigned long long u64;

// ---------------- packed f32x2 helpers (bitwise == scalar rn) ----------------
static __device__ __forceinline__ u64 pk2(float lo, float hi) {
    u64 r; asm("mov.b64 %0, {%1,%2};" : "=l"(r) : "f"(lo), "f"(hi)); return r;
}
static __device__ __forceinline__ void upk2(u64 v, float& lo, float& hi) {
    asm("mov.b64 {%0,%1}, %2;" : "=f"(lo), "=f"(hi) : "l"(v));
}
static __device__ __forceinline__ u64 add2(u64 a, u64 b) {
    u64 r; asm("add.rn.f32x2 %0, %1, %2;" : "=l"(r) : "l"(a), "l"(b)); return r;
}
static __device__ __forceinline__ u64 mul2(u64 a, u64 b) {
    u64 r; asm("mul.rn.f32x2 %0, %1, %2;" : "=l"(r) : "l"(a), "l"(b)); return r;
}

// ---------------- cluster / DSMEM helpers ----------------
static __device__ __forceinline__ unsigned smem_u32(const void* p) {
    return (unsigned)__cvta_generic_to_shared(p);
}
static __device__ __forceinline__ unsigned my_ctarank() {
    unsigned r; asm("mov.u32 %0, %%cluster_ctarank;" : "=r"(r)); return r;
}
static __device__ __forceinline__ void dsmem_st_u64(unsigned addr, unsigned rank, u64 v) {
    asm volatile(
        "{\n\t.reg .b32 r;\n\t"
        "mapa.shared::cluster.u32 r, %0, %1;\n\t"
        "st.shared::cluster.u64 [r], %2;\n\t}"
        :: "r"(addr), "r"(rank), "l"(v) : "memory");
}
static __device__ __forceinline__ void dsmem_st_f32(unsigned addr, unsigned rank, float v) {
    asm volatile(
        "{\n\t.reg .b32 r;\n\t"
        "mapa.shared::cluster.u32 r, %0, %1;\n\t"
        "st.shared::cluster.f32 [r], %2;\n\t}"
        :: "r"(addr), "r"(rank), "f"(v) : "memory");
}
static __device__ __forceinline__ void mbar_arrive_remote(unsigned addr, unsigned rank) {
    asm volatile(
        "{\n\t.reg .b32 r;\n\t"
        "mapa.shared::cluster.u32 r, %0, %1;\n\t"
        "mbarrier.arrive.release.cluster.shared::cluster.b64 _, [r];\n\t}"
        :: "r"(addr), "r"(rank) : "memory");
}
static __device__ __forceinline__ void mbar_wait(unsigned addr, unsigned parity) {
    asm volatile(
        "{\n\t.reg .pred P;\n"
        "LW%=:\n\t"
        "mbarrier.try_wait.parity.acquire.cluster.shared::cta.b64 P, [%0], %1;\n\t"
        "@!P bra LW%=;\n\t}"
        :: "r"(addr), "r"(parity) : "memory");
}
#define CLUSTER_SYNC() do { \
    asm volatile("barrier.cluster.arrive.aligned;" ::: "memory"); \
    asm volatile("barrier.cluster.wait.aligned;" ::: "memory"); \
} while (0)

// ------------------------------- kernel -------------------------------
__global__ __launch_bounds__(TPB, 1) __cluster_dims__(CLUSTERSZ, 1, 1)
void fps_contact_kernel(const float* __restrict__ mesh,
                        const float* __restrict__ cmap,
                        const int* __restrict__ initf,
                        float* __restrict__ out,
                        int B, int N, int npoint)
{
    extern __shared__ float dsm[];
    float* xB  = dsm;
    float* yB  = dsm + BSLOTS;
    float* zB  = dsm + 2 * BSLOTS;
    float* pdB = dsm + 3 * BSLOTS;

    // per-warp winners
    __shared__ u64    sh_wkeyA[16];
    __shared__ u64    sh_wkeyB[16];
    __shared__ float4 sh_wxyzB[16];
    // cluster exchange slots, double-buffered
    __shared__ u64    sh_ckeyA[2][CLUSTERSZ];
    __shared__ u64    sh_ckeyB[2][CLUSTERSZ];
    __shared__ u64    sh_cxyB[2][CLUSTERSZ];
    __shared__ float  sh_czB[2][CLUSTERSZ];
    // stats scratch
    __shared__ float  sh_wsum[16][6];
    __shared__ float  sh_wmax[16][2];
    __shared__ u64    sh_sxyA[CLUSTERSZ]; __shared__ float sh_szA[CLUSTERSZ];
    __shared__ u64    sh_sxyB[CLUSTERSZ]; __shared__ float sh_szB[CLUSTERSZ];
    __shared__ float  sh_smaxA[CLUSTERSZ]; __shared__ float sh_smaxB[CLUSTERSZ];
    // selected indices
    __shared__ int    sh_fpsA[MAXNP];
    __shared__ int    sh_fpsB[MAXNP];
    __shared__ u64    mbarA, mbarB;

    const unsigned rank = my_ctarank();
    const int cl   = blockIdx.x / CLUSTERSZ;     // cluster id
    const int bA   = 2 * cl;
    const int bBi  = 2 * cl + 1;
    const bool hasB = (bBi < B);
    const int tid  = threadIdx.x;
    const int lane = tid & 31;
    const int wid  = tid >> 5;
    const int t    = (int)rank * TPB + tid;
    const unsigned mbA_addr = smem_u32(&mbarA);
    const unsigned mbB_addr = smem_u32(&mbarB);

    const float* mA = mesh + (size_t)bA * N * 3;
    const float* mB = mesh + (size_t)bBi * N * 3;
    if (npoint > MAXNP) npoint = MAXNP;

    if (tid == 0) {
        asm volatile("mbarrier.init.shared::cta.b64 [%0], %1;"
                     :: "r"(mbA_addr), "r"(CLUSTERSZ) : "memory");
        asm volatile("mbarrier.init.shared::cta.b64 [%0], %1;"
                     :: "r"(mbB_addr), "r"(CLUSTERSZ) : "memory");
    }

    // ---------------- batch A: load into registers ----------------------------
    u64   PX[NPAIR], PY[NPAIR], PZ[NPAIR];
    float PDa[NPAIR], PDb[NPAIR];
    float sxA = 0.f, syA = 0.f, szA = 0.f;

#pragma unroll
    for (int q = 0; q < NPAIR; q++) {
        const int p0 = t + (2 * q) * STRIDE;
        const int p1 = t + (2 * q + 1) * STRIDE;
        const bool v0 = p0 < N, v1 = p1 < N;
        float x0 = 0.f, y0 = 0.f, z0 = 0.f, x1 = 0.f, y1 = 0.f, z1 = 0.f;
        if (v0) { x0 = mA[(size_t)p0 * 3 + 0]; y0 = mA[(size_t)p0 * 3 + 1]; z0 = mA[(size_t)p0 * 3 + 2]; }
        if (v1) { x1 = mA[(size_t)p1 * 3 + 0]; y1 = mA[(size_t)p1 * 3 + 1]; z1 = mA[(size_t)p1 * 3 + 2]; }
        PX[q] = pk2(x0, x1); PY[q] = pk2(y0, y1); PZ[q] = pk2(z0, z1);
        PDa[q] = v0 ? BIGF : 0.0f;
        PDb[q] = v1 ? BIGF : 0.0f;
        sxA += x0 + x1; syA += y0 + y1; szA += z0 + z1;
    }

    // ---------------- batch B: load into SMEM ---------------------------------
    float sxB = 0.f, syB = 0.f, szB2 = 0.f;
    if (hasB) {
#pragma unroll
        for (int s = 0; s < NSLOTB; s++) {
            const int p = t + s * STRIDE;
            const bool v = (s < NSLOTB - 1) || (p < N);
            float x = 0.f, y = 0.f, z = 0.f;
            if (v) { x = mB[(size_t)p * 3 + 0]; y = mB[(size_t)p * 3 + 1]; z = mB[(size_t)p * 3 + 2]; }
            const int o = s * TPB + tid;
            xB[o] = x; yB[o] = y; zB[o] = z;
            pdB[o] = v ? BIGF : 0.0f;
            sxB += x; syB += y; szB2 += z;
        }
    }

    // ---------------- means (both batches, one reduce round) ------------------
#pragma unroll
    for (int off = 16; off; off >>= 1) {
        sxA += __shfl_xor_sync(0xffffffffu, sxA, off);
        syA += __shfl_xor_sync(0xffffffffu, syA, off);
        szA += __shfl_xor_sync(0xffffffffu, szA, off);
        sxB += __shfl_xor_sync(0xffffffffu, sxB, off);
        syB += __shfl_xor_sync(0xffffffffu, syB, off);
        szB2 += __shfl_xor_sync(0xffffffffu, szB2, off);
    }
    if (lane == 0) {
        sh_wsum[wid][0] = sxA; sh_wsum[wid][1] = syA; sh_wsum[wid][2] = szA;
        sh_wsum[wid][3] = sxB; sh_wsum[wid][4] = syB; sh_wsum[wid][5] = szB2;
    }
    __syncthreads();
    if (wid == 0) {
        float v0 = (lane < 16) ? sh_wsum[lane][0] : 0.f;
        float v1 = (lane < 16) ? sh_wsum[lane][1] : 0.f;
        float v2 = (lane < 16) ? sh_wsum[lane][2] : 0.f;
        float v3 = (lane < 16) ? sh_wsum[lane][3] : 0.f;
        float v4 = (lane < 16) ? sh_wsum[lane][4] : 0.f;
        float v5 = (lane < 16) ? sh_wsum[lane][5] : 0.f;
#pragma unroll
        for (int off = 8; off; off >>= 1) {
            v0 += __shfl_xor_sync(0xffffffffu, v0, off);
            v1 += __shfl_xor_sync(0xffffffffu, v1, off);
            v2 += __shfl_xor_sync(0xffffffffu, v2, off);
            v3 += __shfl_xor_sync(0xffffffffu, v3, off);
            v4 += __shfl_xor_sync(0xffffffffu, v4, off);
            v5 += __shfl_xor_sync(0xffffffffu, v5, off);
        }
        if (lane < CLUSTERSZ) {
            dsmem_st_u64(smem_u32(&sh_sxyA[rank]), lane, pk2(v0, v1));
            dsmem_st_f32(smem_u32(&sh_szA[rank]),  lane, v2);
            dsmem_st_u64(smem_u32(&sh_sxyB[rank]), lane, pk2(v3, v4));
            dsmem_st_f32(smem_u32(&sh_szB[rank]),  lane, v5);
        }
    }
    CLUSTER_SYNC();   // also publishes mbarrier inits cluster-wide

    float txA = 0.f, tyA = 0.f, tzA = 0.f, txB = 0.f, tyB = 0.f, tzB = 0.f;
#pragma unroll
    for (int r = 0; r < CLUSTERSZ; r++) {
        float a, c; upk2(sh_sxyA[r], a, c);
        txA += a; tyA += c; tzA += sh_szA[r];
        upk2(sh_sxyB[r], a, c);
        txB += a; tyB += c; tzB += sh_szB[r];
    }
    const float cmxA = txA / (float)N, cmyA = tyA / (float)N, cmzA = tzA / (float)N;
    const float cmxB = txB / (float)N, cmyB = tyB / (float)N, cmzB = tzB / (float)N;

    // ---------------- s_obj for both batches ----------------------------------
    {
        u64 nmx = pk2(-cmxA, -cmxA), nmy = pk2(-cmyA, -cmyA), nmz = pk2(-cmzA, -cmzA);
        float mdA = 0.f;
#pragma unroll
        for (int q = 0; q < NPAIR; q++) {
            u64 dx = add2(PX[q], nmx);
            u64 dy = add2(PY[q], nmy);
            u64 dz = add2(PZ[q], nmz);
            u64 ss = add2(add2(mul2(dx, dx), mul2(dy, dy)), mul2(dz, dz));
            float d0, d1; upk2(ss, d0, d1);
            if (PDa[q] != 0.0f) mdA = fmaxf(mdA, d0);
            if (PDb[q] != 0.0f) mdA = fmaxf(mdA, d1);
        }
        float mdB = 0.f;
        if (hasB) {
#pragma unroll
            for (int s = 0; s < NSLOTB; s++) {
                const int o = s * TPB + tid;
                float dx = __fadd_rn(xB[o], -cmxB);
                float dy = __fadd_rn(yB[o], -cmyB);
                float dz = __fadd_rn(zB[o], -cmzB);
                float ds = __fadd_rn(__fadd_rn(__fmul_rn(dx, dx), __fmul_rn(dy, dy)),
                                     __fmul_rn(dz, dz));
                if (pdB[o] != 0.0f) mdB = fmaxf(mdB, ds);
            }
        }
#pragma unroll
        for (int off = 16; off; off >>= 1) {
            mdA = fmaxf(mdA, __shfl_xor_sync(0xffffffffu, mdA, off));
            mdB = fmaxf(mdB, __shfl_xor_sync(0xffffffffu, mdB, off));
        }
        if (lane == 0) { sh_wmax[wid][0] = mdA; sh_wmax[wid][1] = mdB; }
        __syncthreads();
        if (wid == 0) {
            float a = (lane < 16) ? sh_wmax[lane][0] : 0.f;
            float c = (lane < 16) ? sh_wmax[lane][1] : 0.f;
#pragma unroll
            for (int off = 8; off; off >>= 1) {
                a = fmaxf(a, __shfl_xor_sync(0xffffffffu, a, off));
                c = fmaxf(c, __shfl_xor_sync(0xffffffffu, c, off));
            }
            if (lane < CLUSTERSZ) {
                dsmem_st_f32(smem_u32(&sh_smaxA[rank]), lane, a);
                dsmem_st_f32(smem_u32(&sh_smaxB[rank]), lane, c);
            }
        }
        CLUSTER_SYNC();
    }
    float mxA = 0.f, mxB = 0.f;
#pragma unroll
    for (int r = 0; r < CLUSTERSZ; r++) {
        mxA = fmaxf(mxA, sh_smaxA[r]);
        mxB = fmaxf(mxB, sh_smaxB[r]);
    }
    const float s_objA = sqrtf(mxA);
    const float s_objB = sqrtf(mxB);

    // ---------------- FPS pipelined main loops --------------------------------
    int fA = initf[bA];
    u64 ncx, ncy, ncz;
    {
        float ix = __ldg(mA + (size_t)fA * 3 + 0);
        float iy = __ldg(mA + (size_t)fA * 3 + 1);
        float iz = __ldg(mA + (size_t)fA * 3 + 2);
        ncx = pk2(-ix, -ix); ncy = pk2(-iy, -iy); ncz = pk2(-iz, -iz);
    }
    int fB = 0;
    float nbx = 0.f, nby = 0.f, nbz = 0.f;
    if (hasB) {
        fB = initf[bBi];
        nbx = -__ldg(mB + (size_t)fB * 3 + 0);
        nby = -__ldg(mB + (size_t)fB * 3 + 1);
        nbz = -__ldg(mB + (size_t)fB * 3 + 2);
    }
    if (rank == 0 && tid == 0) {
        sh_fpsA[0] = fA;
        if (hasB) sh_fpsB[0] = fB;
    }
    int parA = 0, parB = 0;
    unsigned phA = 0, phB = 0;

    // ======= prologue: scan+push round 0 for both batches =======
    if (npoint > 1) {
        // --- scan A ---
        {
            float best0 = -1.0f, best1 = -1.0f;
            int   bs0 = 0, bs1 = 1;
#pragma unroll
            for (int q = 0; q < NPAIR; q++) {
                u64 dx = add2(PX[q], ncx);
                u64 dy = add2(PY[q], ncy);
                u64 dz = add2(PZ[q], ncz);
                u64 ss = add2(add2(mul2(dx, dx), mul2(dy, dy)), mul2(dz, dz));
                float d0, d1; upk2(ss, d0, d1);
                float n0 = fminf(PDa[q], d0); PDa[q] = n0;
                if (n0 > best0) { best0 = n0; bs0 = 2 * q; }
                float n1 = fminf(PDb[q], d1); PDb[q] = n1;
                if (n1 > best1) { best1 = n1; bs1 = 2 * q + 1; }
            }
            float best; int bs;
            if (best1 > best0 || (best1 == best0 && bs1 < bs0)) { best = best1; bs = bs1; }
            else                                                { best = best0; bs = bs0; }
            const unsigned bits = __float_as_uint(best);
            const unsigned wmax = __reduce_max_sync(0xffffffffu, bits);
            const unsigned gidx = (unsigned)t + ((unsigned)bs << 12);
            const unsigned cand = (bits == wmax) ? gidx : 0xffffffffu;
            const unsigned wmin = __reduce_min_sync(0xffffffffu, cand);
            if (cand == wmin) sh_wkeyA[wid] = ((u64)wmax << 32) | (unsigned)(~wmin);
        }
        __syncthreads();
        if (tid < CLUSTERSZ) {
            u64 bk = sh_wkeyA[0];
#pragma unroll
            for (int w = 1; w < 16; w++) { u64 k2 = sh_wkeyA[w]; if (k2 > bk) bk = k2; }
            dsmem_st_u64(smem_u32(&sh_ckeyA[parA][rank]), (unsigned)tid, bk);
            mbar_arrive_remote(mbA_addr, (unsigned)tid);
        }
        // --- scan B ---
        if (hasB) {
            float best0 = -1.0f, best1 = -1.0f;
            int   bs0 = 0, bs1 = 1;
#pragma unroll
            for (int s = 0; s < NSLOTB; s++) {
                const int o = s * TPB + tid;
                float dx = __fadd_rn(xB[o], nbx);
                float dy = __fadd_rn(yB[o], nby);
                float dz = __fadd_rn(zB[o], nbz);
                float ds = __fadd_rn(__fadd_rn(__fmul_rn(dx, dx), __fmul_rn(dy, dy)),
                                     __fmul_rn(dz, dz));
                float n = fminf(pdB[o], ds); pdB[o] = n;
                if (s & 1) { if (n > best1) { best1 = n; bs1 = s; } }
                else       { if (n > best0) { best0 = n; bs0 = s; } }
            }
            float best; int bs;
            if (best1 > best0 || (best1 == best0 && bs1 < bs0)) { best = best1; bs = bs1; }
            else                                                { best = best0; bs = bs0; }
            const unsigned bits = __float_as_uint(best);
            const unsigned wmax = __reduce_max_sync(0xffffffffu, bits);
            const unsigned gidx = (unsigned)t + ((unsigned)bs << 12);
            const unsigned cand = (bits == wmax) ? gidx : 0xffffffffu;
            const unsigned wmin = __reduce_min_sync(0xffffffffu, cand);
            if (cand == wmin) {
                sh_wkeyB[wid] = ((u64)wmax << 32) | (unsigned)(~wmin);
                const int o = bs * TPB + tid;
                sh_wxyzB[wid] = make_float4(xB[o], yB[o], zB[o], 0.f);
            }
            __syncthreads();
            if (tid < CLUSTERSZ) {
                u64 bk = sh_wkeyB[0]; int j = 0;
#pragma unroll
                for (int w = 1; w < 16; w++) { u64 k2 = sh_wkeyB[w]; if (k2 > bk) { bk = k2; j = w; } }
                float4 p = sh_wxyzB[j];
                dsmem_st_u64(smem_u32(&sh_ckeyB[parB][rank]), (unsigned)tid, bk);
                dsmem_st_u64(smem_u32(&sh_cxyB[parB][rank]),  (unsigned)tid, pk2(p.x, p.y));
                dsmem_st_f32(smem_u32(&sh_czB[parB][rank]),   (unsigned)tid, p.z);
                mbar_arrive_remote(mbB_addr, (unsigned)tid);
            }
        }
    }

    // ======= steady-state rounds =======
    for (int i = 1; i < npoint; i++) {
        // ---- finish A round i-1 ----
        mbar_wait(mbA_addr, phA); phA ^= 1;
        {
            u64 bk = sh_ckeyA[parA][0];
#pragma unroll
            for (int r = 1; r < CLUSTERSZ; r++) { u64 k2 = sh_ckeyA[parA][r]; if (k2 > bk) bk = k2; }
            fA = (int)(~(unsigned)bk);
        }
        parA ^= 1;
        if (rank == 0 && tid == 0) sh_fpsA[i] = fA;
        {
            float bx = __ldg(mA + (size_t)fA * 3 + 0);
            float by = __ldg(mA + (size_t)fA * 3 + 1);
            float bz = __ldg(mA + (size_t)fA * 3 + 2);
            ncx = pk2(-bx, -bx); ncy = pk2(-by, -by); ncz = pk2(-bz, -bz);
        }
        // ---- scan+push A round i (not needed after last centroid) ----
        if (i + 1 < npoint) {
            float best0 = -1.0f, best1 = -1.0f;
            int   bs0 = 0, bs1 = 1;
#pragma unroll
            for (int q = 0; q < NPAIR; q++) {
                u64 dx = add2(PX[q], ncx);
                u64 dy = add2(PY[q], ncy);
                u64 dz = add2(PZ[q], ncz);
                u64 ss = add2(add2(mul2(dx, dx), mul2(dy, dy)), mul2(dz, dz));
                float d0, d1; upk2(ss, d0, d1);
                float n0 = fminf(PDa[q], d0); PDa[q] = n0;
                if (n0 > best0) { best0 = n0; bs0 = 2 * q; }
                float n1 = fminf(PDb[q], d1); PDb[q] = n1;
                if (n1 > best1) { best1 = n1; bs1 = 2 * q + 1; }
            }
            float best; int bs;
            if (best1 > best0 || (best1 == best0 && bs1 < bs0)) { best = best1; bs = bs1; }
            else                                                { best = best0; bs = bs0; }
            const unsigned bits = __float_as_uint(best);
            const unsigned wmax = __reduce_max_sync(0xffffffffu, bits);
            const unsigned gidx = (unsigned)t + ((unsigned)bs << 12);
            const unsigned cand = (bits == wmax) ? gidx : 0xffffffffu;
            const unsigned wmin = __reduce_min_sync(0xffffffffu, cand);
            if (cand == wmin) sh_wkeyA[wid] = ((u64)wmax << 32) | (unsigned)(~wmin);
            __syncthreads();
            if (tid < CLUSTERSZ) {
                u64 bk = sh_wkeyA[0];
#pragma unroll
                for (int w = 1; w < 16; w++) { u64 k2 = sh_wkeyA[w]; if (k2 > bk) bk = k2; }
                dsmem_st_u64(smem_u32(&sh_ckeyA[parA][rank]), (unsigned)tid, bk);
                mbar_arrive_remote(mbA_addr, (unsigned)tid);
            }
        }
        // ---- finish B round i-1 + scan+push B round i ----
        if (hasB) {
            mbar_wait(mbB_addr, phB); phB ^= 1;
            int br = 0;
            {
                u64 bk = sh_ckeyB[parB][0];
#pragma unroll
                for (int r = 1; r < CLUSTERSZ; r++) {
                    u64 k2 = sh_ckeyB[parB][r];
                    if (k2 > bk) { bk = k2; br = r; }
                }
                fB = (int)(~(unsigned)bk);
            }
            if (rank == 0 && tid == 0) sh_fpsB[i] = fB;
            {
                float bx, by; upk2(sh_cxyB[parB][br], bx, by);
                float bz = sh_czB[parB][br];
                nbx = -bx; nby = -by; nbz = -bz;
            }
            parB ^= 1;
            if (i + 1 < npoint) {
                float best0 = -1.0f, best1 = -1.0f;
                int   bs0 = 0, bs1 = 1;
#pragma unroll
                for (int s = 0; s < NSLOTB; s++) {
                    const int o = s * TPB + tid;
                    float dx = __fadd_rn(xB[o], nbx);
                    float dy = __fadd_rn(yB[o], nby);
                    float dz = __fadd_rn(zB[o], nbz);
                    float ds = __fadd_rn(__fadd_rn(__fmul_rn(dx, dx), __fmul_rn(dy, dy)),
                                         __fmul_rn(dz, dz));
                    float n = fminf(pdB[o], ds); pdB[o] = n;
                    if (s & 1) { if (n > best1) { best1 = n; bs1 = s; } }
                    else       { if (n > best0) { best0 = n; bs0 = s; } }
                }
                float best; int bs;
                if (best1 > best0 || (best1 == best0 && bs1 < bs0)) { best = best1; bs = bs1; }
                else                                                { best = best0; bs = bs0; }
                const unsigned bits = __float_as_uint(best);
                const unsigned wmax = __reduce_max_sync(0xffffffffu, bits);
                const unsigned gidx = (unsigned)t + ((unsigned)bs << 12);
                const unsigned cand = (bits == wmax) ? gidx : 0xffffffffu;
                const unsigned wmin = __reduce_min_sync(0xffffffffu, cand);
                if (cand == wmin) {
                    sh_wkeyB[wid] = ((u64)wmax << 32) | (unsigned)(~wmin);
                    const int o = bs * TPB + tid;
                    sh_wxyzB[wid] = make_float4(xB[o], yB[o], zB[o], 0.f);
                }
                __syncthreads();
                if (tid < CLUSTERSZ) {
                    u64 bk = sh_wkeyB[0]; int j = 0;
#pragma unroll
                    for (int w = 1; w < 16; w++) { u64 k2 = sh_wkeyB[w]; if (k2 > bk) { bk = k2; j = w; } }
                    float4 p = sh_wxyzB[j];
                    dsmem_st_u64(smem_u32(&sh_ckeyB[parB][rank]), (unsigned)tid, bk);
                    dsmem_st_u64(smem_u32(&sh_cxyB[parB][rank]),  (unsigned)tid, pk2(p.x, p.y));
                    dsmem_st_f32(smem_u32(&sh_czB[parB][rank]),   (unsigned)tid, p.z);
                    mbar_arrive_remote(mbB_addr, (unsigned)tid);
                }
            }
        }
    }

    __syncthreads();

    // ---------------- gather + write output (rank-0 CTA) ----------------------
    if (rank == 0) {
        for (int i = tid; i < npoint; i += TPB) {
            const int idx = sh_fpsA[i];
            const float x = mA[(size_t)idx * 3 + 0];
            const float y = mA[(size_t)idx * 3 + 1];
            const float z = mA[(size_t)idx * 3 + 2];
            const float c = cmap[(size_t)bA * N + idx];
            reinterpret_cast<float4*>(out)[(size_t)bA * npoint + i] =
                make_float4(c, x / s_objA, y / s_objA, z / s_objA);
        }
        if (hasB) {
            for (int i = tid; i < npoint; i += TPB) {
                const int idx = sh_fpsB[i];
                const float x = mB[(size_t)idx * 3 + 0];
                const float y = mB[(size_t)idx * 3 + 1];
                const float z = mB[(size_t)idx * 3 + 2];
                const float c = cmap[(size_t)bBi * N + idx];
                reinterpret_cast<float4*>(out)[(size_t)bBi * npoint + i] =
                    make_float4(c, x / s_objB, y / s_objB, z / s_objB);
            }
        }
    }
}

// ------------------------------- launch -------------------------------
extern "C" void kernel_launch(void* const* d_in, const int* in_sizes, int n_in,
                              void* d_out, int out_size) {
    const float* mesh  = (const float*)d_in[0];
    const float* cmap  = (const float*)d_in[1];
    const int*   initf = (const int*)d_in[2];

    const int B = in_sizes[2];
    const int N = in_sizes[0] / (3 * B);
    const int npoint = out_size / (4 * B);   // out = [B, npoint, 4] float32

    const int dyn_smem = 4 * BSLOTS * (int)sizeof(float);   // 204800 B
    cudaFuncSetAttribute(fps_contact_kernel,
                         cudaFuncAttributeMaxDynamicSharedMemorySize, dyn_smem);

    dim3 grid(((B + 1) / 2) * CLUSTERSZ);
    dim3 block(TPB);
    fps_contact_kernel<<<grid, block, dyn_smem>>>(mesh, cmap, initf,
                                                  (float*)d_out, B, N, npoint);
}